// round 6
// baseline (speedup 1.0000x reference)
#include <cuda_runtime.h>
#include <cstdint>

#define NTOK 16384
#define DIN 64
#define DOUT 64
#define NC 512
#define KSEL 16
#define NASSIGN (NTOK*KSEL)

typedef unsigned long long u64;

// ---------------- scratch (device globals: no allocation allowed) -------------
__device__ float g_ctrT[DIN*NC];        // centers transposed [k][c]
__device__ float g_scores[NASSIGN];     // softmax scores per (token, j)
__device__ int   g_idx[NASSIGN];        // selected center per (token, j)
__device__ int   g_cnt[NC];
__device__ int   g_off[NC];
__device__ int   g_cursor[NC];
__device__ int   g_tok[NASSIGN];        // bucket -> token id
__device__ float g_ascore[NASSIGN];     // bucket -> score
__device__ int   g_dslot[NASSIGN];      // bucket -> (token*16+j) destination slot
__device__ float g_part[(size_t)NASSIGN*DOUT]; // 67 MB partials, slot-addressed
__device__ float g_c2[NC];              // ||c||^2 + 1024 bias
__device__ int   g_tiles[8192];         // (center, rowStart) pairs
__device__ int   g_ntiles;
__device__ int   g_work;                // dynamic tile cursor for k_gemm
__device__ int   g_flag;                // scan-done flag for k_ss

// ---------------- packed f32x2 helpers ----------------------------------------
__device__ __forceinline__ u64 dupf(float x){
    u64 r; asm("mov.b64 %0, {%1, %1};" : "=l"(r) : "f"(x)); return r;
}
__device__ __forceinline__ void ffma2(u64 &d, u64 a, u64 b){
    asm("fma.rn.f32x2 %0, %1, %2, %0;" : "+l"(d) : "l"(a), "l"(b));
}
__device__ __forceinline__ u64 ffma2v(u64 a, u64 b, u64 c){
    u64 d; asm("fma.rn.f32x2 %0, %1, %2, %3;" : "=l"(d) : "l"(a), "l"(b), "l"(c)); return d;
}
__device__ __forceinline__ u64 fadd2(u64 a, u64 b){
    u64 r; asm("add.rn.f32x2 %0, %1, %2;" : "=l"(r) : "l"(a), "l"(b)); return r;
}
__device__ __forceinline__ u64 fmul2(u64 a, u64 b){
    u64 r; asm("mul.rn.f32x2 %0, %1, %2;" : "=l"(r) : "l"(a), "l"(b)); return r;
}

// ---------------- K0: transpose centers, c2 (+bias), zero counters -------------
__global__ void k_prep(const float* __restrict__ ctrs){
    int bid = blockIdx.x, tid = threadIdx.x;
    if(bid < 128){
        int e = bid*256 + tid;           // 32768 elements
        int k = e >> 9, c = e & 511;
        g_ctrT[k*NC + c] = ctrs[c*DIN + k];
    } else {
        int c = (bid-128)*256 + tid;     // 512 centers over 2 blocks
        g_cnt[c] = 0;
        if(c == 0){ g_work = 0; g_flag = 0; }
        const float4* c4 = (const float4*)ctrs;
        float s = 1024.0f;  // bias keeps keys > 0; cancels in softmax
        #pragma unroll
        for(int seg=0; seg<16; seg++){
            float4 v = c4[c*16 + seg];
            s += v.x*v.x + v.y*v.y + v.z*v.z + v.w*v.w;
        }
        g_c2[c] = s;
    }
}

// ---------------- K1: fused distance GEMM + top-16 + softmax + counts ----------
__global__ __launch_bounds__(256,2) void k_fused(const float* __restrict__ x){
    extern __shared__ char smraw[];
    float* xs  = (float*)smraw;            // 32*64   swizzled x tile
    float* ds  = xs + 32*64;               // 32*512  distance keys
    float* sdf = ds + 32*512;              // 8*16    selected keys
    int*   sci = (int*)(sdf + 8*16);       // 8*16    selected centers

    int tid = threadIdx.x;
    int ttile = blockIdx.x*32;

    const float4* x4 = (const float4*)x;
    #pragma unroll
    for(int it=0; it<2; it++){
        int idx2 = tid + 256*it;
        int rr = idx2 >> 4, seg = idx2 & 15;
        float4 v = x4[(ttile+rr)*16 + seg];
        *(float4*)&xs[rr*64 + ((seg*4) ^ ((rr&3)*8))] = v;
    }
    __syncthreads();

    int w  = tid >> 5, lane = tid & 31;
    int og = lane & 7, tg = lane >> 3;     // tg in 0..3
    int cbase = w*64 + og*8;
    int xsw = tg*8;

    u64 acc[8][4];
    #pragma unroll
    for(int i=0;i<8;i++){ acc[i][0]=0; acc[i][1]=0; acc[i][2]=0; acc[i][3]=0; }

    #pragma unroll 4
    for(int k4=0;k4<16;k4++){
        float v4[8][4];
        #pragma unroll
        for(int i=0;i<8;i++)
            *(float4*)v4[i] = *(const float4*)&xs[(tg+4*i)*64 + ((k4*4) ^ xsw)];
        #pragma unroll
        for(int kk=0;kk<4;kk++){
            int k = k4*4 + kk;
            ulonglong2 p0 = *(const ulonglong2*)&g_ctrT[k*NC + cbase];
            ulonglong2 p1 = *(const ulonglong2*)&g_ctrT[k*NC + cbase + 4];
            #pragma unroll
            for(int i=0;i<8;i++){
                u64 xv = dupf(v4[i][kk]);
                ffma2(acc[i][0], xv, p0.x);
                ffma2(acc[i][1], xv, p0.y);
                ffma2(acc[i][2], xv, p1.x);
                ffma2(acc[i][3], xv, p1.y);
            }
        }
    }
    {
        ulonglong2 q0 = *(const ulonglong2*)&g_c2[cbase];
        ulonglong2 q1 = *(const ulonglong2*)&g_c2[cbase + 4];
        u64 m2 = dupf(-2.0f);
        #pragma unroll
        for(int i=0;i<8;i++){
            int r = tg + 4*i;
            ulonglong2* dst = (ulonglong2*)&ds[r*NC + cbase];
            dst[0] = make_ulonglong2(ffma2v(acc[i][0], m2, q0.x),
                                     ffma2v(acc[i][1], m2, q0.y));
            dst[1] = make_ulonglong2(ffma2v(acc[i][2], m2, q1.x),
                                     ffma2v(acc[i][3], m2, q1.y));
        }
    }
    __syncthreads();

    float* sd  = sdf + w*16;
    int*   sc  = sci + w*16;
    for(int tt=0; tt<4; tt++){
        int t = w*4 + tt;
        float v[16];
        #pragma unroll
        for(int i=0;i<16;i++) v[i] = ds[t*NC + lane + 32*i];

        float lmin = v[0]; int larg = 0;
        #pragma unroll
        for(int i=1;i<16;i++){ if(v[i] < lmin){ lmin=v[i]; larg=i; } }

        #pragma unroll 1
        for(int j=0;j<16;j++){
            unsigned mb   = __reduce_min_sync(0xffffffffu, __float_as_uint(lmin));
            unsigned ball = __ballot_sync(0xffffffffu, __float_as_uint(lmin) == mb);
            int wlan = __ffs(ball) - 1;
            if(lane == wlan){
                sd[j] = lmin;
                sc[j] = larg*32 + lane;
                v[larg] = 3.0e38f;
                lmin = v[0]; larg = 0;
                #pragma unroll
                for(int i=1;i<16;i++){ if(v[i] < lmin){ lmin=v[i]; larg=i; } }
            }
            __syncwarp();
        }
        if(lane < 16){
            float d = sd[lane];
            float m = sd[0];
            float e = expf(m - d);
            float s = e;
            #pragma unroll
            for(int o=8;o>=1;o>>=1) s += __shfl_xor_sync(0x0000ffffu, s, o);
            float scv = e / s;
            int c = sc[lane];
            int gt = ttile + t;
            g_scores[gt*16 + lane] = scv;
            g_idx[gt*16 + lane]    = c;
            atomicAdd(&g_cnt[c], 1);
        }
        __syncwarp();
    }
}

// ---------------- K2: fused scan (block 0) + scatter (all 512 blocks) ----------
__global__ __launch_bounds__(512) void k_ss(){
    __shared__ int wsum[16];
    int tid = threadIdx.x;

    if(blockIdx.x == 0){
        int c = tid, lane = c & 31, w = c >> 5;
        int cn = g_cnt[c];
        int s = cn;
        #pragma unroll
        for(int o=1;o<32;o<<=1){ int v=__shfl_up_sync(0xffffffffu,s,o); if(lane>=o) s+=v; }
        if(lane==31) wsum[w] = s;
        __syncthreads();
        if(w==0){
            int t = (lane<16) ? wsum[lane] : 0;
            #pragma unroll
            for(int o=1;o<16;o<<=1){ int v=__shfl_up_sync(0xffffffffu,t,o); if(lane>=o) t+=v; }
            if(lane<16) wsum[lane] = t;
        }
        __syncthreads();
        int inc = s + ((w>0) ? wsum[w-1] : 0);
        g_off[c] = inc - cn;
        g_cursor[c] = inc - cn;

        int t = (cn + 127) >> 7;
        __syncthreads();
        int s2 = t;
        #pragma unroll
        for(int o=1;o<32;o<<=1){ int v=__shfl_up_sync(0xffffffffu,s2,o); if(lane>=o) s2+=v; }
        if(lane==31) wsum[w] = s2;
        __syncthreads();
        if(w==0){
            int tt = (lane<16) ? wsum[lane] : 0;
            #pragma unroll
            for(int o=1;o<16;o<<=1){ int v=__shfl_up_sync(0xffffffffu,tt,o); if(lane>=o) tt+=v; }
            if(lane<16) wsum[lane] = tt;
        }
        __syncthreads();
        int tinc = s2 + ((w>0) ? wsum[w-1] : 0);
        int tb = tinc - t;
        for(int i=0;i<t;i++){
            g_tiles[2*(tb+i)]   = c;
            g_tiles[2*(tb+i)+1] = i << 7;
        }
        if(c == 511) g_ntiles = tinc;
        __threadfence();
        __syncthreads();
        if(tid == 0) *((volatile int*)&g_flag) = 1;
    } else {
        if(tid == 0){ while(*((volatile int*)&g_flag) == 0){ } }
        __syncthreads();
    }

    int a = blockIdx.x*512 + tid;          // (token<<4)|j
    int c = g_idx[a];
    float s = g_scores[a];
    int pos = atomicAdd(&g_cursor[c], 1);
    g_tok[pos]   = a >> 4;
    g_ascore[pos]= s;
    g_dslot[pos] = a;
}

// ---------------- K3: grouped GEMM per (center, 128-row tile) ------------------
// 128 thr, thread tile 8 rows x 8 cols (cols split og*4 / og*4+32).
// Warp w owns rows [32w, 32w+32): whole-warp skip when 32w >= m.
__global__ __launch_bounds__(128,4) void k_gemm(const float* __restrict__ x,
                                                const float* __restrict__ Wv,
                                                const float* __restrict__ Ov){
    __shared__ float ws[DIN*DOUT];   // ws[k*64 + p] (row-major copy of Wv[c])
    __shared__ float xs[128*DIN];    // xs[r*64 + (k ^ 8*((r>>3)&3))]
    __shared__ int s_tile;
    int nt = g_ntiles;
    int tid = threadIdx.x;
    int og = tid & 7, tg = tid >> 3;     // tg 0..15, rows tg*8..tg*8+7
    int w  = tid >> 5;
    int xsw = (tg & 3) * 8;              // rows tg*8+i share (r>>3)&3 == tg&3
    const float4* x4 = (const float4*)x;

    while(true){
        __syncthreads();             // smem reuse + s_tile protection
        if(tid == 0) s_tile = atomicAdd(&g_work, 1);
        __syncthreads();
        int tile = s_tile;
        if(tile >= nt) break;

        int c      = g_tiles[2*tile];
        int rstart = g_tiles[2*tile+1];
        int base   = g_off[c] + rstart;
        int m      = g_cnt[c] - rstart; if(m > 128) m = 128;

        const float4* wv4 = (const float4*)(Wv + (size_t)c*4096);
        float4* ws4 = (float4*)ws;
        #pragma unroll
        for(int f=0; f<8; f++) ws4[tid + 128*f] = wv4[tid + 128*f];

        #pragma unroll
        for(int it=0; it<16; it++){
            int idx2 = tid + 128*it;
            int rr = idx2 >> 4, seg = idx2 & 15;
            if(rr < m){
                float4 v = x4[g_tok[base+rr]*16 + seg];
                *(float4*)&xs[rr*64 + ((seg*4) ^ (((rr>>3)&3)*8))] = v;
            }
        }
        __syncthreads();

        if(32*w < m){                   // warp-uniform: skip padded rows
            u64 acc[8][4];
            #pragma unroll
            for(int i=0;i<8;i++){ acc[i][0]=0; acc[i][1]=0; acc[i][2]=0; acc[i][3]=0; }

            #pragma unroll 2
            for(int k4=0;k4<16;k4++){
                float v4[8][4];
                #pragma unroll
                for(int i=0;i<8;i++)
                    *(float4*)v4[i] = *(const float4*)&xs[(tg*8+i)*64 + ((k4*4) ^ xsw)];
                #pragma unroll
                for(int kk=0;kk<4;kk++){
                    int k = k4*4 + kk;
                    ulonglong2 p0 = *(const ulonglong2*)&ws[k*64 + og*4];
                    ulonglong2 p1 = *(const ulonglong2*)&ws[k*64 + og*4 + 32];
                    #pragma unroll
                    for(int i=0;i<8;i++){
                        u64 xv = dupf(v4[i][kk]);
                        ffma2(acc[i][0], xv, p0.x);
                        ffma2(acc[i][1], xv, p0.y);
                        ffma2(acc[i][2], xv, p1.x);
                        ffma2(acc[i][3], xv, p1.y);
                    }
                }
            }
            ulonglong2 q0 = *(const ulonglong2*)&Ov[(size_t)c*64 + og*4];
            ulonglong2 q1 = *(const ulonglong2*)&Ov[(size_t)c*64 + og*4 + 32];
            #pragma unroll
            for(int i=0;i<8;i++){
                int r = tg*8 + i;
                if(r < m){
                    int slot = g_dslot[base + r];
                    u64 sv = dupf(g_ascore[base + r]);
                    ulonglong2* d0 = (ulonglong2*)&g_part[(size_t)slot*64 + og*4];
                    ulonglong2* d1 = (ulonglong2*)&g_part[(size_t)slot*64 + og*4 + 32];
                    *d0 = make_ulonglong2(fmul2(fadd2(acc[i][0], q0.x), sv),
                                          fmul2(fadd2(acc[i][1], q0.y), sv));
                    *d1 = make_ulonglong2(fmul2(fadd2(acc[i][2], q1.x), sv),
                                          fmul2(fadd2(acc[i][3], q1.y), sv));
                }
            }
        }
    }
}

// ---------------- K4: streamed reduce of 16 contiguous partials per token ------
__global__ __launch_bounds__(256) void k_reduce(float* __restrict__ out){
    int t  = blockIdx.x*16 + (threadIdx.x >> 4);
    int c4 = threadIdx.x & 15;
    const float4* p = (const float4*)(g_part + (size_t)t*16*64) + c4;
    float4 acc = make_float4(0.f,0.f,0.f,0.f);
    #pragma unroll
    for(int j=0;j<16;j++){
        float4 v = p[j*16];
        acc.x += v.x; acc.y += v.y; acc.z += v.z; acc.w += v.w;
    }
    ((float4*)out)[t*16 + c4] = acc;
}

// ---------------- launch -------------------------------------------------------
extern "C" void kernel_launch(void* const* d_in, const int* in_sizes, int n_in,
                              void* d_out, int out_size){
    const float* x    = (const float*)d_in[0];
    const float* ctrs = (const float*)d_in[1];
    const float* Wv   = (const float*)d_in[2];
    const float* Ov   = (const float*)d_in[3];
    float* out = (float*)d_out;

    const int FUSED_SMEM = (32*64 + 32*512 + 8*16)*4 + 8*16*4;
    cudaFuncSetAttribute(k_fused, cudaFuncAttributeMaxDynamicSharedMemorySize,
                         FUSED_SMEM);

    k_prep  <<<130, 256>>>(ctrs);
    k_fused <<<512, 256, FUSED_SMEM>>>(x);
    k_ss    <<<512, 512>>>();
    k_gemm  <<<592, 128>>>(x, Wv, Ov);
    k_reduce<<<1024, 256>>>(out);
}